// round 1
// baseline (speedup 1.0000x reference)
#include <cuda_runtime.h>
#include <math.h>

#define B_ 32
#define DIM 384
#define DEPTH 12
#define NCLS 1000
#define PDIM 768
#define NPATCH 576
#define NTOK 577
#define EPSV 1e-5f

// ---------------- scratch (no allocations allowed) ----------------
__device__ float g_patch[B_ * NPATCH * PDIM];     // normalized patches
__device__ float g_emb[B_ * NPATCH * DIM];        // patch embeddings (pre-LN2)
__device__ float g_x[B_ * NTOK * DIM];            // residual stream
__device__ float g_q[B_ * NTOK * DIM];
__device__ float g_k[B_ * NTOK * DIM];
__device__ float g_v[B_ * NTOK * DIM];
__device__ float g_attnT[B_ * NTOK * NTOK];       // transposed scores / attn
__device__ float g_wv[DEPTH * DIM * DIM];         // precomputed value weights

// ---------------- block reductions ----------------
__device__ __forceinline__ float blk_sum(float v, float* sm) {
    int lane = threadIdx.x & 31, w = threadIdx.x >> 5;
#pragma unroll
    for (int o = 16; o; o >>= 1) v += __shfl_xor_sync(0xffffffffu, v, o);
    if (lane == 0) sm[w] = v;
    __syncthreads();
    int nw = blockDim.x >> 5;
    if (threadIdx.x < 32) {
        v = (lane < nw) ? sm[lane] : 0.f;
#pragma unroll
        for (int o = 16; o; o >>= 1) v += __shfl_xor_sync(0xffffffffu, v, o);
        if (lane == 0) sm[0] = v;
    }
    __syncthreads();
    float r = sm[0];
    __syncthreads();
    return r;
}

__device__ __forceinline__ float blk_max(float v, float* sm) {
    int lane = threadIdx.x & 31, w = threadIdx.x >> 5;
#pragma unroll
    for (int o = 16; o; o >>= 1) v = fmaxf(v, __shfl_xor_sync(0xffffffffu, v, o));
    if (lane == 0) sm[w] = v;
    __syncthreads();
    int nw = blockDim.x >> 5;
    if (threadIdx.x < 32) {
        v = (lane < nw) ? sm[lane] : -INFINITY;
#pragma unroll
        for (int o = 16; o; o >>= 1) v = fmaxf(v, __shfl_xor_sync(0xffffffffu, v, o));
        if (lane == 0) sm[0] = v;
    }
    __syncthreads();
    float r = sm[0];
    __syncthreads();
    return r;
}

// ---------------- wv = (softmax(lv, axis=0)/DIM).T  per layer ----------------
// block = (col j, layer l), 384 threads over rows i.  wv[l][j][i] = S[i][j].
__global__ void compute_wv_kernel(const float* __restrict__ lv, float* __restrict__ wv) {
    __shared__ float sm[32];
    int j = blockIdx.x, l = blockIdx.y, i = threadIdx.x;
    float v = lv[(l * DIM + i) * DIM + j];
    float mx = blk_max(v, sm);
    float e = expf(v - mx);
    float s = blk_sum(e, sm);
    wv[(l * DIM + j) * DIM + i] = e / (s * (float)DIM);
}

// ---------------- patchify + LN1 ----------------
// block = (patch p, batch b), 256 threads, 3 features each (PDIM=768)
__global__ void patchify_ln1_kernel(const float* __restrict__ img,
                                    const float* __restrict__ g1,
                                    const float* __restrict__ b1,
                                    float* __restrict__ out) {
    __shared__ float sm[32];
    int p = blockIdx.x, b = blockIdx.y;
    int ph = p / 24, pw = p % 24;
    float vals[3];
    float s = 0.f, ss = 0.f;
#pragma unroll
    for (int r = 0; r < 3; r++) {
        int f = threadIdx.x + r * 256;
        int py = f / 48, rem = f % 48;
        int px = rem / 3, c = rem % 3;
        float v = img[((b * 3 + c) * 384 + ph * 16 + py) * 384 + pw * 16 + px];
        vals[r] = v;
        s += v; ss += v * v;
    }
    s = blk_sum(s, sm);
    ss = blk_sum(ss, sm);
    float mu = s * (1.f / PDIM);
    float var = ss * (1.f / PDIM) - mu * mu;
    float rstd = rsqrtf(var + EPSV);
    float* op = out + (b * NPATCH + p) * PDIM;
#pragma unroll
    for (int r = 0; r < 3; r++) {
        int f = threadIdx.x + r * 256;
        op[f] = (vals[r] - mu) * rstd * g1[f] + b1[f];
    }
}

// ---------------- LN2 + pos + cls assembly ----------------
// block = (token t, batch b), 384 threads over d
__global__ void assemble_x_kernel(const float* __restrict__ emb,
                                  const float* __restrict__ g2,
                                  const float* __restrict__ b2,
                                  const float* __restrict__ pos,
                                  const float* __restrict__ cls,
                                  float* __restrict__ x) {
    __shared__ float sm[32];
    int t = blockIdx.x, b = blockIdx.y, d = threadIdx.x;
    float v;
    if (t == 0) {
        v = cls[d] + pos[d];
    } else {
        float e = emb[(b * NPATCH + (t - 1)) * DIM + d];
        float s = blk_sum(e, sm);
        float ss = blk_sum(e * e, sm);
        float mu = s * (1.f / DIM);
        float var = ss * (1.f / DIM) - mu * mu;
        float rstd = rsqrtf(var + EPSV);
        v = (e - mu) * rstd * g2[d] + b2[d] + pos[t * DIM + d];
    }
    x[(b * NTOK + t) * DIM + d] = v;
}

// ---------------- tiled SGEMM ----------------
// C[M,N] (+epi) = A * B.  TRANS_A: A stored [K][M]; TRANS_B: B stored [N][K].
// EPI: 0 = plain, 1 = +bias[n], 2 = *alpha, 3 = 0.5*acc + 0.5*Xold (residual mix)
#define BM 64
#define BN 64
#define BK 16
template <int TRANS_A, int TRANS_B, int EPI>
__global__ void gemm_kernel(const float* __restrict__ A, const float* __restrict__ Bm,
                            float* __restrict__ C, int M, int N, int K,
                            long long sA, long long sB, long long sC,
                            const float* __restrict__ bias, float alpha,
                            const float* __restrict__ Xold, long long sX) {
    int batch = blockIdx.z;
    A += (long long)batch * sA;
    Bm += (long long)batch * sB;
    C += (long long)batch * sC;
    __shared__ float As[BK][BM + 1];
    __shared__ float Bs[BK][BN + 1];
    int m0 = blockIdx.y * BM;
    int n0 = blockIdx.x * BN;
    int tid = threadIdx.x;
    int tr = tid >> 4, tc = tid & 15;       // 16x16 threads, 4x4 microtile
    float acc[4][4] = {};

    for (int k0 = 0; k0 < K; k0 += BK) {
#pragma unroll
        for (int i = tid; i < BM * BK; i += 256) {
            int mm, kk;
            if (TRANS_A) { kk = i / BM; mm = i % BM; }
            else         { mm = i / BK; kk = i % BK; }
            int gm = m0 + mm, gk = k0 + kk;
            float v = 0.f;
            if (gm < M && gk < K)
                v = TRANS_A ? A[(long long)gk * M + gm] : A[(long long)gm * K + gk];
            As[kk][mm] = v;
        }
#pragma unroll
        for (int i = tid; i < BN * BK; i += 256) {
            int nn, kk;
            if (TRANS_B) { nn = i / BK; kk = i % BK; }
            else         { kk = i / BN; nn = i % BN; }
            int gn = n0 + nn, gk = k0 + kk;
            float v = 0.f;
            if (gn < N && gk < K)
                v = TRANS_B ? Bm[(long long)gn * K + gk] : Bm[(long long)gk * N + gn];
            Bs[kk][nn] = v;
        }
        __syncthreads();
#pragma unroll
        for (int kk = 0; kk < BK; kk++) {
            float a[4], b[4];
#pragma unroll
            for (int i = 0; i < 4; i++) a[i] = As[kk][tr * 4 + i];
#pragma unroll
            for (int j = 0; j < 4; j++) b[j] = Bs[kk][tc * 4 + j];
#pragma unroll
            for (int i = 0; i < 4; i++)
#pragma unroll
                for (int j = 0; j < 4; j++)
                    acc[i][j] = fmaf(a[i], b[j], acc[i][j]);
        }
        __syncthreads();
    }

#pragma unroll
    for (int i = 0; i < 4; i++) {
        int gm = m0 + tr * 4 + i;
        if (gm >= M) continue;
#pragma unroll
        for (int j = 0; j < 4; j++) {
            int gn = n0 + tc * 4 + j;
            if (gn >= N) continue;
            float v = acc[i][j];
            if (EPI == 1) v += bias[gn];
            if (EPI == 2) v *= alpha;
            if (EPI == 3) v = 0.5f * v + 0.5f * Xold[(long long)batch * sX + (long long)gm * N + gn];
            C[(long long)gm * N + gn] = v;
        }
    }
}

// ---------------- row softmax on attnT minus identity ----------------
// attnT[b][j][i]: softmax over i (contiguous), subtract (i==j).
__global__ void softmax_sub_eye_kernel(float* __restrict__ attnT) {
    __shared__ float sm[32];
    long long row = blockIdx.x;
    int j = (int)(row % NTOK);
    float* p = attnT + row * NTOK;
    float vals[3];
    float mx = -INFINITY;
#pragma unroll
    for (int r = 0; r < 3; r++) {
        int i = threadIdx.x + r * 256;
        vals[r] = (i < NTOK) ? p[i] : -INFINITY;
        mx = fmaxf(mx, vals[r]);
    }
    mx = blk_max(mx, sm);
    float s = 0.f;
#pragma unroll
    for (int r = 0; r < 3; r++) {
        vals[r] = (vals[r] == -INFINITY) ? 0.f : expf(vals[r] - mx);
        s += vals[r];
    }
    s = blk_sum(s, sm);
    float inv = 1.f / s;
#pragma unroll
    for (int r = 0; r < 3; r++) {
        int i = threadIdx.x + r * 256;
        if (i < NTOK) p[i] = vals[r] * inv - (i == j ? 1.f : 0.f);
    }
}

// ---------------- classifier head on token 0 ----------------
// grid (8, B), 128 threads: c = bx*128+tid
__global__ void head_kernel(const float* __restrict__ x,
                            const float* __restrict__ Wh,
                            const float* __restrict__ bh,
                            float* __restrict__ out) {
    __shared__ float xr[DIM];
    int b = blockIdx.y;
    const float* xp = x + (long long)b * NTOK * DIM;   // token 0 row
#pragma unroll
    for (int r = 0; r < 3; r++) xr[threadIdx.x + r * 128] = xp[threadIdx.x + r * 128];
    __syncthreads();
    int c = blockIdx.x * 128 + threadIdx.x;
    if (c >= NCLS) return;
    float acc = bh[c];
    for (int f = 0; f < DIM; f++) acc = fmaf(xr[f], Wh[f * NCLS + c], acc);
    out[b * NCLS + c] = acc;
}

// ---------------- launch ----------------
extern "C" void kernel_launch(void* const* d_in, const int* in_sizes, int n_in,
                              void* d_out, int out_size) {
    const float* img  = (const float*)d_in[0];
    const float* ln1g = (const float*)d_in[1];
    const float* ln1b = (const float*)d_in[2];
    const float* Wp   = (const float*)d_in[3];
    const float* bp   = (const float*)d_in[4];
    const float* ln2g = (const float*)d_in[5];
    const float* ln2b = (const float*)d_in[6];
    const float* pos  = (const float*)d_in[7];
    const float* cls  = (const float*)d_in[8];
    const float* wk   = (const float*)d_in[9];
    const float* wq   = (const float*)d_in[10];
    const float* wvr  = (const float*)d_in[11];
    const float* Wh   = (const float*)d_in[12];
    const float* bh   = (const float*)d_in[13];
    float* out = (float*)d_out;

    float *patch, *emb, *x, *q, *k, *v, *attnT, *wv;
    cudaGetSymbolAddress((void**)&patch, g_patch);
    cudaGetSymbolAddress((void**)&emb,   g_emb);
    cudaGetSymbolAddress((void**)&x,     g_x);
    cudaGetSymbolAddress((void**)&q,     g_q);
    cudaGetSymbolAddress((void**)&k,     g_k);
    cudaGetSymbolAddress((void**)&v,     g_v);
    cudaGetSymbolAddress((void**)&attnT, g_attnT);
    cudaGetSymbolAddress((void**)&wv,    g_wv);

    const float scale = (float)(1.0 / sqrt((double)NTOK));
    const int MTOK = B_ * NTOK;       // 18464
    const int MPAT = B_ * NPATCH;     // 18432

    // value-weight precompute + patch pipeline
    compute_wv_kernel<<<dim3(DIM, DEPTH), 384>>>(wvr, wv);
    patchify_ln1_kernel<<<dim3(NPATCH, B_), 256>>>(img, ln1g, ln1b, patch);
    gemm_kernel<0, 0, 1><<<dim3((DIM + BN - 1) / BN, (MPAT + BM - 1) / BM, 1), 256>>>(
        patch, Wp, emb, MPAT, DIM, PDIM, 0, 0, 0, bp, 1.f, nullptr, 0);
    assemble_x_kernel<<<dim3(NTOK, B_), 384>>>(emb, ln2g, ln2b, pos, cls, x);

    dim3 gProj((DIM + BN - 1) / BN, (MTOK + BM - 1) / BM, 1);
    dim3 gScore((NTOK + BN - 1) / BN, (NTOK + BM - 1) / BM, B_);
    dim3 gOut((DIM + BN - 1) / BN, (NTOK + BM - 1) / BM, B_);
    const long long sTD = (long long)NTOK * DIM;
    const long long sTT = (long long)NTOK * NTOK;

    for (int l = 0; l < DEPTH; l++) {
        const float* lq = wq  + (long long)l * DIM * DIM;
        const float* lk = wk  + (long long)l * DIM * DIM;
        const float* lw = wv  + (long long)l * DIM * DIM;
        gemm_kernel<0, 0, 0><<<gProj, 256>>>(x, lq, q, MTOK, DIM, DIM, 0, 0, 0, nullptr, 1.f, nullptr, 0);
        gemm_kernel<0, 0, 0><<<gProj, 256>>>(x, lk, k, MTOK, DIM, DIM, 0, 0, 0, nullptr, 1.f, nullptr, 0);
        gemm_kernel<0, 0, 0><<<gProj, 256>>>(x, lw, v, MTOK, DIM, DIM, 0, 0, 0, nullptr, 1.f, nullptr, 0);
        // scoresT[b][j][i] = scale * k[b,j] . q[b,i]   (NT gemm, batched)
        gemm_kernel<0, 1, 2><<<gScore, 256>>>(k, q, attnT, NTOK, NTOK, DIM,
                                              sTD, sTD, sTT, nullptr, scale, nullptr, 0);
        softmax_sub_eye_kernel<<<B_ * NTOK, 256>>>(attnT);
        // x = 0.5 * (attnT^T @ v) + 0.5 * x   (TN gemm, batched, fused residual)
        gemm_kernel<1, 0, 3><<<gOut, 256>>>(attnT, v, x, NTOK, DIM, NTOK,
                                            sTT, sTD, sTD, nullptr, 1.f, x, sTD);
    }

    head_kernel<<<dim3(8, B_), 128>>>(x, Wh, bh, out);
}

// round 3
// speedup vs baseline: 1.9841x; 1.9841x over previous
#include <cuda_runtime.h>
#include <math.h>
#include <stdint.h>

#define B_ 32
#define DIM 384
#define DEPTH 12
#define NCLS 1000
#define PDIM 768
#define NPATCH 576
#define NTOK 577
#define EPSV 1e-5f

// ---------------- scratch (no allocations allowed) ----------------
__device__ float g_patch[B_ * NPATCH * PDIM];
__device__ float g_emb[B_ * NPATCH * DIM];
__device__ float g_x[B_ * NTOK * DIM];
__device__ float g_q[B_ * NTOK * DIM];
__device__ float g_k[B_ * NTOK * DIM];
__device__ float g_v[B_ * NTOK * DIM];
__device__ float g_attnT[B_ * NTOK * NTOK];
__device__ float g_wv[DEPTH * DIM * DIM];

// ---------------- block reductions ----------------
__device__ __forceinline__ float blk_sum(float v, float* sm) {
    int lane = threadIdx.x & 31, w = threadIdx.x >> 5;
#pragma unroll
    for (int o = 16; o; o >>= 1) v += __shfl_xor_sync(0xffffffffu, v, o);
    if (lane == 0) sm[w] = v;
    __syncthreads();
    int nw = blockDim.x >> 5;
    if (threadIdx.x < 32) {
        v = (lane < nw) ? sm[lane] : 0.f;
#pragma unroll
        for (int o = 16; o; o >>= 1) v += __shfl_xor_sync(0xffffffffu, v, o);
        if (lane == 0) sm[0] = v;
    }
    __syncthreads();
    float r = sm[0];
    __syncthreads();
    return r;
}

__device__ __forceinline__ float blk_max(float v, float* sm) {
    int lane = threadIdx.x & 31, w = threadIdx.x >> 5;
#pragma unroll
    for (int o = 16; o; o >>= 1) v = fmaxf(v, __shfl_xor_sync(0xffffffffu, v, o));
    if (lane == 0) sm[w] = v;
    __syncthreads();
    int nw = blockDim.x >> 5;
    if (threadIdx.x < 32) {
        v = (lane < nw) ? sm[lane] : -INFINITY;
#pragma unroll
        for (int o = 16; o; o >>= 1) v = fmaxf(v, __shfl_xor_sync(0xffffffffu, v, o));
        if (lane == 0) sm[0] = v;
    }
    __syncthreads();
    float r = sm[0];
    __syncthreads();
    return r;
}

// ---------------- wv = (softmax(lv, axis=0)/DIM).T per layer ----------------
__global__ void compute_wv_kernel(const float* __restrict__ lv, float* __restrict__ wv) {
    __shared__ float sm[32];
    int j = blockIdx.x, l = blockIdx.y, i = threadIdx.x;
    float v = lv[(l * DIM + i) * DIM + j];
    float mx = blk_max(v, sm);
    float e = expf(v - mx);
    float s = blk_sum(e, sm);
    wv[(l * DIM + j) * DIM + i] = e / (s * (float)DIM);
}

// ---------------- patchify + LN1 ----------------
__global__ void patchify_ln1_kernel(const float* __restrict__ img,
                                    const float* __restrict__ g1,
                                    const float* __restrict__ b1,
                                    float* __restrict__ out) {
    __shared__ float sm[32];
    int p = blockIdx.x, b = blockIdx.y;
    int ph = p / 24, pw = p % 24;
    float vals[3];
    float s = 0.f, ss = 0.f;
#pragma unroll
    for (int r = 0; r < 3; r++) {
        int f = threadIdx.x + r * 256;
        int py = f / 48, rem = f % 48;
        int px = rem / 3, c = rem % 3;
        float v = img[((b * 3 + c) * 384 + ph * 16 + py) * 384 + pw * 16 + px];
        vals[r] = v;
        s += v; ss += v * v;
    }
    s = blk_sum(s, sm);
    ss = blk_sum(ss, sm);
    float mu = s * (1.f / PDIM);
    float var = ss * (1.f / PDIM) - mu * mu;
    float rstd = rsqrtf(var + EPSV);
    float* op = out + (b * NPATCH + p) * PDIM;
#pragma unroll
    for (int r = 0; r < 3; r++) {
        int f = threadIdx.x + r * 256;
        op[f] = (vals[r] - mu) * rstd * g1[f] + b1[f];
    }
}

// ---------------- LN2 + pos + cls assembly ----------------
__global__ void assemble_x_kernel(const float* __restrict__ emb,
                                  const float* __restrict__ g2,
                                  const float* __restrict__ b2,
                                  const float* __restrict__ pos,
                                  const float* __restrict__ cls,
                                  float* __restrict__ x) {
    __shared__ float sm[32];
    int t = blockIdx.x, b = blockIdx.y, d = threadIdx.x;
    float v;
    if (t == 0) {
        v = cls[d] + pos[d];
    } else {
        float e = emb[(b * NPATCH + (t - 1)) * DIM + d];
        float s = blk_sum(e, sm);
        float ss = blk_sum(e * e, sm);
        float mu = s * (1.f / DIM);
        float var = ss * (1.f / DIM) - mu * mu;
        float rstd = rsqrtf(var + EPSV);
        v = (e - mu) * rstd * g2[d] + b2[d] + pos[t * DIM + d];
    }
    x[(b * NTOK + t) * DIM + d] = v;
}

// ---------------- 3xTF32 tensor-core GEMM ----------------
// C[M,N] = A*B (+epi). TRANS_A: A stored [K][M]; TRANS_B: B stored [N][K].
// EPI: 0 plain, 1 +bias[n], 2 *alpha, 3 0.5*acc+0.5*Xold
#define BM 128
#define BN 64
#define BK 16
#define APAD 8
#define BPAD 8

__device__ __forceinline__ void split_tf32(float a, uint32_t& hi, uint32_t& lo) {
    uint32_t h;
    asm("cvt.rna.tf32.f32 %0, %1;" : "=r"(h) : "f"(a));
    float rl = a - __uint_as_float(h);
    uint32_t l;
    asm("cvt.rna.tf32.f32 %0, %1;" : "=r"(l) : "f"(rl));
    hi = h; lo = l;
}

__device__ __forceinline__ void mma_tf32(float* d, const uint32_t* a, const uint32_t* b) {
    asm volatile(
        "mma.sync.aligned.m16n8k8.row.col.f32.tf32.tf32.f32 "
        "{%0,%1,%2,%3}, {%4,%5,%6,%7}, {%8,%9}, {%0,%1,%2,%3};"
        : "+f"(d[0]), "+f"(d[1]), "+f"(d[2]), "+f"(d[3])
        : "r"(a[0]), "r"(a[1]), "r"(a[2]), "r"(a[3]), "r"(b[0]), "r"(b[1]));
}

template <int TRANS_A, int TRANS_B, int EPI>
__global__ __launch_bounds__(256)
void gemm_tc_kernel(const float* __restrict__ A, const float* __restrict__ Bm,
                    float* __restrict__ C, int M, int N, int K,
                    long long sA, long long sB, long long sC,
                    const float* __restrict__ bias, float alpha,
                    const float* __restrict__ Xold, long long sX) {
    int batch = blockIdx.z;
    A += (long long)batch * sA;
    Bm += (long long)batch * sB;
    C += (long long)batch * sC;

    __shared__ float As[BK][BM + APAD];
    __shared__ float Bs[BK][BN + BPAD];

    int m0 = blockIdx.y * BM;
    int n0 = blockIdx.x * BN;
    int tid = threadIdx.x;
    int lane = tid & 31, warp = tid >> 5;
    int wm = warp & 3;        // 4 warps in M -> 32 rows each
    int wn = warp >> 2;       // 2 warps in N -> 32 cols each
    int qr = lane >> 2;       // 0..7
    int qc = lane & 3;        // 0..3

    float acc[2][4][4] = {};

    for (int k0 = 0; k0 < K; k0 += BK) {
#pragma unroll
        for (int i = tid; i < BM * BK; i += 256) {
            int mm, kk;
            if (TRANS_A) { kk = i / BM; mm = i % BM; }
            else         { mm = i / BK; kk = i % BK; }
            int gm = m0 + mm, gk = k0 + kk;
            float v = 0.f;
            if (gm < M && gk < K)
                v = TRANS_A ? A[(long long)gk * M + gm] : A[(long long)gm * K + gk];
            As[kk][mm] = v;
        }
#pragma unroll
        for (int i = tid; i < BN * BK; i += 256) {
            int nn, kk;
            if (TRANS_B) { nn = i / BK; kk = i % BK; }
            else         { kk = i / BN; nn = i % BN; }
            int gn = n0 + nn, gk = k0 + kk;
            float v = 0.f;
            if (gn < N && gk < K)
                v = TRANS_B ? Bm[(long long)gn * K + gk] : Bm[(long long)gk * N + gn];
            Bs[kk][nn] = v;
        }
        __syncthreads();

#pragma unroll
        for (int ks = 0; ks < 2; ks++) {
            int kk0 = ks * 8;
            uint32_t ah[2][4], al[2][4], bh[4][2], bl[4][2];
#pragma unroll
            for (int mt = 0; mt < 2; mt++) {
                int rm = wm * 32 + mt * 16;
                float r0 = As[kk0 + qc][rm + qr];
                float r1 = As[kk0 + qc][rm + qr + 8];
                float r2 = As[kk0 + qc + 4][rm + qr];
                float r3 = As[kk0 + qc + 4][rm + qr + 8];
                split_tf32(r0, ah[mt][0], al[mt][0]);
                split_tf32(r1, ah[mt][1], al[mt][1]);
                split_tf32(r2, ah[mt][2], al[mt][2]);
                split_tf32(r3, ah[mt][3], al[mt][3]);
            }
#pragma unroll
            for (int nt = 0; nt < 4; nt++) {
                int cn = wn * 32 + nt * 8;
                float r0 = Bs[kk0 + qc][cn + qr];
                float r1 = Bs[kk0 + qc + 4][cn + qr];
                split_tf32(r0, bh[nt][0], bl[nt][0]);
                split_tf32(r1, bh[nt][1], bl[nt][1]);
            }
#pragma unroll
            for (int mt = 0; mt < 2; mt++)
#pragma unroll
                for (int nt = 0; nt < 4; nt++) {
                    mma_tf32(acc[mt][nt], ah[mt], bh[nt]);
                    mma_tf32(acc[mt][nt], ah[mt], bl[nt]);
                    mma_tf32(acc[mt][nt], al[mt], bh[nt]);
                }
        }
        __syncthreads();
    }

    // epilogue: C layout of m16n8k8 accumulators
#pragma unroll
    for (int mt = 0; mt < 2; mt++) {
#pragma unroll
        for (int nt = 0; nt < 4; nt++) {
#pragma unroll
            for (int e = 0; e < 4; e++) {
                int gm = m0 + wm * 32 + mt * 16 + qr + (e >> 1) * 8;
                int gn = n0 + wn * 32 + nt * 8 + qc * 2 + (e & 1);
                if (gm >= M || gn >= N) continue;
                float v = acc[mt][nt][e];
                if (EPI == 1) v += bias[gn];
                if (EPI == 2) v *= alpha;
                if (EPI == 3) v = 0.5f * v + 0.5f * __ldg(&Xold[(long long)batch * sX + (long long)gm * N + gn]);
                C[(long long)gm * N + gn] = v;
            }
        }
    }
}

// ---------------- row softmax on attnT minus identity ----------------
__global__ void softmax_sub_eye_kernel(float* __restrict__ attnT) {
    __shared__ float sm[32];
    long long row = blockIdx.x;
    int j = (int)(row % NTOK);
    float* p = attnT + row * NTOK;
    float vals[3];
    float mx = -INFINITY;
#pragma unroll
    for (int r = 0; r < 3; r++) {
        int i = threadIdx.x + r * 256;
        vals[r] = (i < NTOK) ? p[i] : -INFINITY;
        mx = fmaxf(mx, vals[r]);
    }
    mx = blk_max(mx, sm);
    float s = 0.f;
#pragma unroll
    for (int r = 0; r < 3; r++) {
        vals[r] = (vals[r] == -INFINITY) ? 0.f : expf(vals[r] - mx);
        s += vals[r];
    }
    s = blk_sum(s, sm);
    float inv = 1.f / s;
#pragma unroll
    for (int r = 0; r < 3; r++) {
        int i = threadIdx.x + r * 256;
        if (i < NTOK) p[i] = vals[r] * inv - (i == j ? 1.f : 0.f);
    }
}

// ---------------- classifier head on token 0 ----------------
__global__ void head_kernel(const float* __restrict__ x,
                            const float* __restrict__ Wh,
                            const float* __restrict__ bh,
                            float* __restrict__ out) {
    __shared__ float xr[DIM];
    int b = blockIdx.y;
    const float* xp = x + (long long)b * NTOK * DIM;
#pragma unroll
    for (int r = 0; r < 3; r++) xr[threadIdx.x + r * 128] = xp[threadIdx.x + r * 128];
    __syncthreads();
    int c = blockIdx.x * 128 + threadIdx.x;
    if (c >= NCLS) return;
    float acc = bh[c];
    for (int f = 0; f < DIM; f++) acc = fmaf(xr[f], Wh[f * NCLS + c], acc);
    out[b * NCLS + c] = acc;
}

// ---------------- launch ----------------
extern "C" void kernel_launch(void* const* d_in, const int* in_sizes, int n_in,
                              void* d_out, int out_size) {
    const float* img  = (const float*)d_in[0];
    const float* ln1g = (const float*)d_in[1];
    const float* ln1b = (const float*)d_in[2];
    const float* Wp   = (const float*)d_in[3];
    const float* bp   = (const float*)d_in[4];
    const float* ln2g = (const float*)d_in[5];
    const float* ln2b = (const float*)d_in[6];
    const float* pos  = (const float*)d_in[7];
    const float* cls  = (const float*)d_in[8];
    const float* wk   = (const float*)d_in[9];
    const float* wq   = (const float*)d_in[10];
    const float* wvr  = (const float*)d_in[11];
    const float* Wh   = (const float*)d_in[12];
    const float* bh   = (const float*)d_in[13];
    float* out = (float*)d_out;

    float *patch, *emb, *x, *q, *k, *v, *attnT, *wv;
    cudaGetSymbolAddress((void**)&patch, g_patch);
    cudaGetSymbolAddress((void**)&emb,   g_emb);
    cudaGetSymbolAddress((void**)&x,     g_x);
    cudaGetSymbolAddress((void**)&q,     g_q);
    cudaGetSymbolAddress((void**)&k,     g_k);
    cudaGetSymbolAddress((void**)&v,     g_v);
    cudaGetSymbolAddress((void**)&attnT, g_attnT);
    cudaGetSymbolAddress((void**)&wv,    g_wv);

    const float scale = (float)(1.0 / sqrt((double)NTOK));
    const int MTOK = B_ * NTOK;       // 18464
    const int MPAT = B_ * NPATCH;     // 18432

    compute_wv_kernel<<<dim3(DIM, DEPTH), 384>>>(wvr, wv);
    patchify_ln1_kernel<<<dim3(NPATCH, B_), 256>>>(img, ln1g, ln1b, patch);
    gemm_tc_kernel<0, 0, 1><<<dim3((DIM + BN - 1) / BN, (MPAT + BM - 1) / BM, 1), 256>>>(
        patch, Wp, emb, MPAT, DIM, PDIM, 0, 0, 0, bp, 1.f, nullptr, 0);
    assemble_x_kernel<<<dim3(NTOK, B_), 384>>>(emb, ln2g, ln2b, pos, cls, x);

    dim3 gProj((DIM + BN - 1) / BN, (MTOK + BM - 1) / BM, 1);
    dim3 gScore((NTOK + BN - 1) / BN, (NTOK + BM - 1) / BM, B_);
    dim3 gOut((DIM + BN - 1) / BN, (NTOK + BM - 1) / BM, B_);
    const long long sTD = (long long)NTOK * DIM;
    const long long sTT = (long long)NTOK * NTOK;

    for (int l = 0; l < DEPTH; l++) {
        const float* lq = wq  + (long long)l * DIM * DIM;
        const float* lk = wk  + (long long)l * DIM * DIM;
        const float* lw = wv  + (long long)l * DIM * DIM;
        gemm_tc_kernel<0, 0, 0><<<gProj, 256>>>(x, lq, q, MTOK, DIM, DIM, 0, 0, 0, nullptr, 1.f, nullptr, 0);
        gemm_tc_kernel<0, 0, 0><<<gProj, 256>>>(x, lk, k, MTOK, DIM, DIM, 0, 0, 0, nullptr, 1.f, nullptr, 0);
        gemm_tc_kernel<0, 0, 0><<<gProj, 256>>>(x, lw, v, MTOK, DIM, DIM, 0, 0, 0, nullptr, 1.f, nullptr, 0);
        // scoresT[b][j][i] = scale * k[b,j] . q[b,i]
        gemm_tc_kernel<0, 1, 2><<<gScore, 256>>>(k, q, attnT, NTOK, NTOK, DIM,
                                                 sTD, sTD, sTT, nullptr, scale, nullptr, 0);
        softmax_sub_eye_kernel<<<B_ * NTOK, 256>>>(attnT);
        // x = 0.5 * (attnT^T @ v) + 0.5 * x
        gemm_tc_kernel<1, 0, 3><<<gOut, 256>>>(attnT, v, x, NTOK, DIM, NTOK,
                                               sTT, sTD, sTD, nullptr, 1.f, x, sTD);
    }

    head_kernel<<<dim3(8, B_), 128>>>(x, Wh, bh, out);
}